// round 3
// baseline (speedup 1.0000x reference)
#include <cuda_runtime.h>

#define NV 8192
#define NC 4096
#define NB 512
#define NE 24576
#define NITER 5
#define EPSF 1e-12f
#define CLIPF (1.0f - 1e-7f)

// Persistent scratch (device globals: allocation-free per harness rules)
__device__ float g_st[NE * NB];    // signed (|tanh(msg/2)|+eps), edge-major [E, B]   ~50 MB
__device__ float g_P[NC * NB];     // per-check signed product of 6 st's [C, B]        ~8 MB
__device__ float g_llrT[NV * NB];  // transposed llr [N, B]                            ~16 MB
__device__ int   g_inv[NE];        // check -> 6 edge ids (sorted ascending)
__device__ int   g_cnt[NC];        // build counters

// ---------------------------------------------------------------- transpose llr
__global__ void transpose_llr(const float* __restrict__ llr) {
    __shared__ float tile[32][33];
    int tx = threadIdx.x, ty = threadIdx.y;       // block (32, 8)
    int vtile = blockIdx.x * 32;                   // grid.x = NV/32
    int btile = blockIdx.y * 32;                   // grid.y = NB/32
#pragma unroll
    for (int i = 0; i < 4; i++) {
        int b = btile + ty + i * 8;
        tile[ty + i * 8][tx] = llr[b * NV + vtile + tx];
    }
    __syncthreads();
#pragma unroll
    for (int i = 0; i < 4; i++) {
        int v = vtile + ty + i * 8;
        g_llrT[v * NB + btile + tx] = tile[tx][ty + i * 8];
    }
}

// ---------------------------------------------------------------- inverse map
__global__ void zero_cnt() {
    int i = blockIdx.x * blockDim.x + threadIdx.x;
    if (i < NC) g_cnt[i] = 0;
}

__global__ void build_inv(const int* __restrict__ chk) {
    int e = blockIdx.x * blockDim.x + threadIdx.x;
    if (e < NE) {
        int c = chk[e];
        int s = atomicAdd(&g_cnt[c], 1);
        g_inv[c * 6 + s] = e;
    }
}

__global__ void sort_inv() {
    int c = blockIdx.x * blockDim.x + threadIdx.x;
    if (c >= NC) return;
    int a[6];
#pragma unroll
    for (int k = 0; k < 6; k++) a[k] = g_inv[c * 6 + k];
    // insertion sort (6 elements) -> deterministic ascending-edge product order
#pragma unroll
    for (int i = 1; i < 6; i++) {
#pragma unroll
        for (int j = i; j > 0; j--) {
            if (a[j] < a[j - 1]) { int t = a[j]; a[j] = a[j - 1]; a[j - 1] = t; }
        }
    }
#pragma unroll
    for (int k = 0; k < 6; k++) g_inv[c * 6 + k] = a[k];
}

// ---------------------------------------------------------------- iteration 0 var side
// ext == 0  ->  msg = llr for all 3 edges of a var
__global__ void v0_kernel() {
    int b = blockIdx.x * 32 + threadIdx.x;             // grid.x = NB/32
    int v = blockIdx.y * blockDim.y + threadIdx.y;     // grid.y = NV/8, block (32,8)
    float m  = g_llrT[v * NB + b];
    float ex = __expf(m);                              // tanh(m/2) = (e^m-1)/(e^m+1)
    float t  = __fdividef(ex - 1.0f, ex + 1.0f);
    float st = t + copysignf(EPSF, t);
    int e = 3 * v;
    g_st[(e + 0) * NB + b] = st;
    g_st[(e + 1) * NB + b] = st;
    g_st[(e + 2) * NB + b] = st;
}

// ---------------------------------------------------------------- check product
__global__ void c_kernel() {
    int b = blockIdx.x * 32 + threadIdx.x;             // grid.x = NB/32
    int c = blockIdx.y * blockDim.y + threadIdx.y;     // grid.y = NC/8, block (32,8)
    const int* inv = &g_inv[c * 6];
    float p = g_st[inv[0] * NB + b];
#pragma unroll
    for (int k = 1; k < 6; k++) p *= g_st[inv[k] * NB + b];
    g_P[c * NB + b] = p;
}

// ---------------------------------------------------------------- fused check-update(i) + var-update(i+1) + output(i)
__global__ void v_kernel(const int* __restrict__ chk, float* __restrict__ out,
                         int iter, int update) {
    __shared__ float tile[32][33];
    int tx = threadIdx.x, ty = threadIdx.y;            // block (32, 8)
    int b  = blockIdx.x * 32 + tx;                     // grid.x = NB/32
    int v0 = blockIdx.y * 32;                          // grid.y = NV/32

#pragma unroll
    for (int s = 0; s < 4; s++) {
        int vl = s * 8 + ty;
        int v  = v0 + vl;
        int e0 = 3 * v;
        float st0 = g_st[(e0 + 0) * NB + b];
        float st1 = g_st[(e0 + 1) * NB + b];
        float st2 = g_st[(e0 + 2) * NB + b];
        int c0 = chk[e0 + 0], c1 = chk[e0 + 1], c2 = chk[e0 + 2];
        float p0 = g_P[c0 * NB + b];
        float p1 = g_P[c1 * NB + b];
        float p2 = g_P[c2 * NB + b];

        // leave-one-out = (prod of 6 signed st) / st_e  == ref's exp(sum log - log)*signs
        float loo0 = __fdividef(p0, st0);
        float loo1 = __fdividef(p1, st1);
        float loo2 = __fdividef(p2, st2);
        loo0 = fminf(fmaxf(loo0, -CLIPF), CLIPF);
        loo1 = fminf(fmaxf(loo1, -CLIPF), CLIPF);
        loo2 = fminf(fmaxf(loo2, -CLIPF), CLIPF);
        // ext = 2*atanh(x) = ln((1+x)/(1-x))
        float x0 = __logf(__fdividef(1.0f + loo0, 1.0f - loo0));
        float x1 = __logf(__fdividef(1.0f + loo1, 1.0f - loo1));
        float x2 = __logf(__fdividef(1.0f + loo2, 1.0f - loo2));

        float vsum = x0 + x1 + x2;
        float l = g_llrT[v * NB + b];
        tile[vl][tx] = vsum + l;                       // out for this iteration

        if (update) {
            // next-iteration messages and st
            float m0 = (vsum - x0) + l;
            float m1 = (vsum - x1) + l;
            float m2 = (vsum - x2) + l;
            float ea = __expf(m0), eb = __expf(m1), ec = __expf(m2);
            float t0 = __fdividef(ea - 1.0f, ea + 1.0f);
            float t1 = __fdividef(eb - 1.0f, eb + 1.0f);
            float t2 = __fdividef(ec - 1.0f, ec + 1.0f);
            g_st[(e0 + 0) * NB + b] = t0 + copysignf(EPSF, t0);
            g_st[(e0 + 1) * NB + b] = t1 + copysignf(EPSF, t1);
            g_st[(e0 + 2) * NB + b] = t2 + copysignf(EPSF, t2);
        }
    }
    __syncthreads();

    // coalesced transposed write: out[iter][b][v]
    int outbase = iter * (NB * NV) + blockIdx.x * 32 * NV + v0;
#pragma unroll
    for (int r = ty; r < 32; r += 8) {
        out[outbase + r * NV + tx] = tile[tx][r];
    }
}

// ---------------------------------------------------------------- launch
extern "C" void kernel_launch(void* const* d_in, const int* in_sizes, int n_in,
                              void* d_out, int out_size) {
    const float* llr = (const float*)d_in[0];
    // d_in[1] = var_index: structured as repeat(arange(NV), 3) -> not needed
    const int* chk = (const int*)d_in[2];
    float* out = (float*)d_out;

    dim3 blk(32, 8);
    transpose_llr<<<dim3(NV / 32, NB / 32), blk>>>(llr);
    zero_cnt<<<(NC + 255) / 256, 256>>>();
    build_inv<<<(NE + 255) / 256, 256>>>(chk);
    sort_inv<<<(NC + 255) / 256, 256>>>();
    v0_kernel<<<dim3(NB / 32, NV / 8), blk>>>();

    for (int i = 0; i < NITER; i++) {
        c_kernel<<<dim3(NB / 32, NC / 8), blk>>>();
        v_kernel<<<dim3(NB / 32, NV / 32), blk>>>(chk, out, i, (i < NITER - 1) ? 1 : 0);
    }
}

// round 5
// speedup vs baseline: 1.0636x; 1.0636x over previous
#include <cuda_runtime.h>

#define NV 8192
#define NC 4096
#define NB 512
#define NE 24576
#define NITER 5
#define EPSF 1e-12f
// clip = float(1 - 1e-7) = 1 - 2^-23.  Image of [-clip, clip] under (1+x)/(1-x):
#define RMAXF 16777215.0f      // = 2^24 - 1
#define RMINF 5.9604648e-8f    // = 1/(2^24 - 1) rounded

// Persistent scratch (device globals: allocation-free per harness rules)
__device__ float  g_st[NE * NB];   // signed (|tanh(msg/2)|+eps), edge-major [E,B]  ~50 MB
__device__ float  g_P[NC * NB];    // per-check signed product of 6 st's [C,B]       ~8 MB
__device__ float2 g_LE[NV * NB];   // {llr, exp(llr)} transposed [N,B]              ~32 MB
__device__ int    g_inv[NE];       // check -> 6 edge ids (atomic order; sorted in regs by consumers)
__device__ int    g_cnt[NC];       // build counters

// ---------------------------------------------------------------- prep: transpose llr, exp(llr), zero counters
__global__ void k_prep(const float* __restrict__ llr) {
    __shared__ float tile[32][33];
    int tx = threadIdx.x, ty = threadIdx.y;        // block (32,8)
    int vt = blockIdx.x * 32;                      // grid.x = NV/32 = 256
    int bt = blockIdx.y * 32;                      // grid.y = NB/32 = 16
#pragma unroll
    for (int i = 0; i < 4; i++)
        tile[ty + i * 8][tx] = llr[(bt + ty + i * 8) * NV + vt + tx];

    // zero the build counters (coverage: 4096 blocks * 256 threads >> NC)
    int gtid = (blockIdx.y * gridDim.x + blockIdx.x) * 256 + ty * 32 + tx;
    if (gtid < NC) g_cnt[gtid] = 0;

    __syncthreads();
#pragma unroll
    for (int i = 0; i < 4; i++) {
        int v = vt + ty + i * 8;
        int b = bt + tx;
        float l = tile[tx][ty + i * 8];
        g_LE[v * NB + b] = make_float2(l, __expf(l));
    }
}

// ---------------------------------------------------------------- inverse map (check -> edges)
__global__ void build_inv(const int* __restrict__ chk) {
    int e = blockIdx.x * blockDim.x + threadIdx.x;
    if (e < NE) {
        int c = chk[e];
        int s = atomicAdd(&g_cnt[c], 1);
        g_inv[c * 6 + s] = e;
    }
}

// ---------------------------------------------------------------- helpers
__device__ __forceinline__ float tanh_half_from_exp(float el) {
    // tanh(m/2) from e^m, plus the reference's sign(t)*eps offset folded in
    float t = __fdividef(el - 1.0f, el + 1.0f);
    return t + copysignf(EPSF, t);
}

__device__ __forceinline__ float clamp_r(float r) {
    return fminf(fmaxf(r, RMINF), RMAXF);
}

// ---------------------------------------------------------------- check product (float4 over batch)
__global__ void c_kernel(int first) {
    int tx = threadIdx.x, ty = threadIdx.y;        // block (32,8)
    int b  = (blockIdx.x * 32 + tx) * 4;           // grid.x = 4  (128 batch-quads)
    int c  = blockIdx.y * 8 + ty;                  // grid.y = NC/8 = 512

    int idx[6];
#pragma unroll
    for (int k = 0; k < 6; k++) idx[k] = g_inv[c * 6 + k];
    // Register insertion sort (ascending edge id) EVERY call — deterministic product
    // order matching segment_sum, with NO shared-state mutation (R3's race removed).
#pragma unroll
    for (int i = 1; i < 6; i++)
#pragma unroll
        for (int j = i; j > 0; j--)
            if (idx[j] < idx[j - 1]) { int t = idx[j]; idx[j] = idx[j - 1]; idx[j - 1] = t; }

    float4 p;
    if (first) {
        // iter-0 st depends only on the variable: recompute from cached e^llr,
        // avoiding a 100 MB st round-trip.
        p = make_float4(1.f, 1.f, 1.f, 1.f);
#pragma unroll
        for (int k = 0; k < 6; k++) {
            int v = idx[k] / 3;
            const float4* le = (const float4*)&g_LE[v * NB + b];  // 4 float2 = 2 float4
            float4 a0 = le[0], a1 = le[1];
            p.x *= tanh_half_from_exp(a0.y);
            p.y *= tanh_half_from_exp(a0.w);
            p.z *= tanh_half_from_exp(a1.y);
            p.w *= tanh_half_from_exp(a1.w);
        }
    } else {
        p = *(const float4*)&g_st[idx[0] * NB + b];
#pragma unroll
        for (int k = 1; k < 6; k++) {
            float4 s = *(const float4*)&g_st[idx[k] * NB + b];
            p.x *= s.x; p.y *= s.y; p.z *= s.z; p.w *= s.w;
        }
    }
    *(float4*)&g_P[c * NB + b] = p;
}

// ---------------------------------------------------------------- fused check-update(i) + var-update(i+1) + output(i)
__global__ void v_kernel(const int* __restrict__ chk, float* __restrict__ out,
                         int iter, int first, int update) {
    __shared__ float tile[32][33];
    int tx = threadIdx.x, ty = threadIdx.y;        // block (32,8)
    int b  = blockIdx.x * 32 + tx;                 // grid.x = NB/32 = 16
    int v0 = blockIdx.y * 32;                      // grid.y = NV/32 = 256

#pragma unroll
    for (int s = 0; s < 4; s++) {
        int vl = s * 8 + ty;
        int v  = v0 + vl;
        int e0 = 3 * v;

        float2 le = g_LE[v * NB + b];
        float l = le.x, EL = le.y;

        float st0, st1, st2;
        if (first) {
            float st = tanh_half_from_exp(EL);     // all 3 edges identical at iter 0
            st0 = st1 = st2 = st;
        } else {
            st0 = g_st[(e0 + 0) * NB + b];
            st1 = g_st[(e0 + 1) * NB + b];
            st2 = g_st[(e0 + 2) * NB + b];
        }
        int c0 = chk[e0 + 0], c1 = chk[e0 + 1], c2 = chk[e0 + 2];
        float p0 = g_P[c0 * NB + b];
        float p1 = g_P[c1 * NB + b];
        float p2 = g_P[c2 * NB + b];

        // r_e = e^{ext_e};  ext = 2*atanh(P/st) = log((st+P)/(st-P)), signs cancel.
        // |P| <= |st| always (each |st_j| <= 1, monotone fp products), so r >= 0;
        // clamp replicates the reference's loo clip exactly.
        float r0 = clamp_r(__fdividef(st0 + p0, st0 - p0));
        float r1 = clamp_r(__fdividef(st1 + p1, st1 - p1));
        float r2 = clamp_r(__fdividef(st2 + p2, st2 - p2));

        float r12 = r1 * r2;
        tile[vl][tx] = l + __logf(r0 * r12);       // out = llr + sum of ext

        if (update) {
            // e^{msg_e} = e^llr * prod of the OTHER two r's  (no exp/log round-trip)
            float u0 = EL * r12;
            float u1 = EL * (r0 * r2);
            float u2 = EL * (r0 * r1);
            g_st[(e0 + 0) * NB + b] = tanh_half_from_exp(u0);
            g_st[(e0 + 1) * NB + b] = tanh_half_from_exp(u1);
            g_st[(e0 + 2) * NB + b] = tanh_half_from_exp(u2);
        }
    }
    __syncthreads();

    // coalesced transposed write: out[iter][b][v]
    int outbase = iter * (NB * NV) + (blockIdx.x * 32) * NV + v0;
#pragma unroll
    for (int r = ty; r < 32; r += 8)
        out[outbase + r * NV + tx] = tile[tx][r];
}

// ---------------------------------------------------------------- launch
extern "C" void kernel_launch(void* const* d_in, const int* in_sizes, int n_in,
                              void* d_out, int out_size) {
    const float* llr = (const float*)d_in[0];
    // d_in[1] = var_index: structured as repeat(arange(NV), 3) -> not needed
    const int* chk = (const int*)d_in[2];
    float* out = (float*)d_out;

    dim3 blk(32, 8);
    k_prep<<<dim3(NV / 32, NB / 32), blk>>>(llr);
    build_inv<<<(NE + 255) / 256, 256>>>(chk);

    for (int i = 0; i < NITER; i++) {
        c_kernel<<<dim3(4, NC / 8), blk>>>(i == 0);
        v_kernel<<<dim3(NB / 32, NV / 32), blk>>>(chk, out, i, i == 0, (i < NITER - 1) ? 1 : 0);
    }
}